// round 14
// baseline (speedup 1.0000x reference)
#include <cuda_runtime.h>
#include <cuda_fp16.h>
#include <cuda_bf16.h>

#define N_NODES 50000
#define D_FEAT  128

// CSR row offsets into the sorted edge list. 50001 ints.
__device__ int g_offsets[N_NODES + 1];

// fp16 copy of x, same linear layout (12.8 MB scratch).
__device__ __half g_xh[(size_t)N_NODES * D_FEAT];

// Kernel C: convert x (fp32) -> g_xh (fp16). Linear, coalesced: each thread
// converts 4 floats (float4 -> 2x half2).
__global__ void convert_kernel(const float4* __restrict__ x4) {
    int i = blockIdx.x * blockDim.x + threadIdx.x;   // over N_NODES*32 float4s
    if (i >= N_NODES * 32) return;
    float4 v = x4[i];
    __half2 h0 = __floats2half2_rn(v.x, v.y);
    __half2 h1 = __floats2half2_rn(v.z, v.w);
    half2* out = reinterpret_cast<half2*>(g_xh) + (size_t)i * 2;
    out[0] = h0;
    out[1] = h1;
}

// Kernel A: boundary-diff scatter, 4 edges per thread via int4.
__global__ void build_offsets_kernel(const int* __restrict__ edge_src, int n_edges) {
    int t = blockIdx.x * blockDim.x + threadIdx.x;
    int e0 = t * 4;
    if (e0 >= n_edges) return;
    int4 s = *reinterpret_cast<const int4*>(edge_src + e0);  // n_edges % 4 == 0
    int prev = (e0 == 0) ? -1 : edge_src[e0 - 1];
    for (int n = prev + 1; n <= s.x; n++) g_offsets[n] = e0;
    for (int n = s.x + 1; n <= s.y; n++) g_offsets[n] = e0 + 1;
    for (int n = s.y + 1; n <= s.z; n++) g_offsets[n] = e0 + 2;
    for (int n = s.z + 1; n <= s.w; n++) g_offsets[n] = e0 + 3;
    if (e0 + 4 >= n_edges) {
        for (int n = s.w + 1; n <= N_NODES; n++) g_offsets[n] = n_edges;
    }
}

// Kernel B: one warp per node. Neighbor rows gathered in fp16 (256B rows:
// half the bytes and half the L1tex line-wavefronts of fp32), accumulated in
// fp32. Self feature read exact from fp32 x. uint2 = 4 halves per lane.
__global__ void __launch_bounds__(64)
graph_pool_kernel(const float4* __restrict__ x,
                  const int* __restrict__ edge_dst,
                  float4* __restrict__ out) {
    int warp_id = (blockIdx.x * blockDim.x + threadIdx.x) >> 5;
    int lane = threadIdx.x & 31;
    if (warp_id >= N_NODES) return;

    // self feature (exact fp32); independent of g_offsets (PDL pre-dep work)
    float4 acc = x[(size_t)warp_id * 32 + lane];

    cudaGridDependencySynchronize();

    int beg = g_offsets[warp_id];
    int end = g_offsets[warp_id + 1];

    const uint2* xh = reinterpret_cast<const uint2*>(g_xh);  // 4 halves/elem

    int e = beg;
    for (; e + 4 <= end; e += 4) {
        int d0 = edge_dst[e + 0];
        int d1 = edge_dst[e + 1];
        int d2 = edge_dst[e + 2];
        int d3 = edge_dst[e + 3];
        uint2 u0 = __ldcg(&xh[(size_t)d0 * 32 + lane]);
        uint2 u1 = __ldcg(&xh[(size_t)d1 * 32 + lane]);
        uint2 u2 = __ldcg(&xh[(size_t)d2 * 32 + lane]);
        uint2 u3 = __ldcg(&xh[(size_t)d3 * 32 + lane]);

        float2 a, b;
        a = __half22float2(*reinterpret_cast<__half2*>(&u0.x));
        b = __half22float2(*reinterpret_cast<__half2*>(&u0.y));
        acc.x += a.x; acc.y += a.y; acc.z += b.x; acc.w += b.y;
        a = __half22float2(*reinterpret_cast<__half2*>(&u1.x));
        b = __half22float2(*reinterpret_cast<__half2*>(&u1.y));
        acc.x += a.x; acc.y += a.y; acc.z += b.x; acc.w += b.y;
        a = __half22float2(*reinterpret_cast<__half2*>(&u2.x));
        b = __half22float2(*reinterpret_cast<__half2*>(&u2.y));
        acc.x += a.x; acc.y += a.y; acc.z += b.x; acc.w += b.y;
        a = __half22float2(*reinterpret_cast<__half2*>(&u3.x));
        b = __half22float2(*reinterpret_cast<__half2*>(&u3.y));
        acc.x += a.x; acc.y += a.y; acc.z += b.x; acc.w += b.y;
    }
    for (; e < end; e++) {
        int d = edge_dst[e];
        uint2 u = __ldcg(&xh[(size_t)d * 32 + lane]);
        float2 a = __half22float2(*reinterpret_cast<__half2*>(&u.x));
        float2 b = __half22float2(*reinterpret_cast<__half2*>(&u.y));
        acc.x += a.x; acc.y += a.y; acc.z += b.x; acc.w += b.y;
    }

    __stcg(&out[(size_t)warp_id * 32 + lane], acc);
}

extern "C" void kernel_launch(void* const* d_in, const int* in_sizes, int n_in,
                              void* d_out, int out_size) {
    const float* x = (const float*)d_in[0];
    const int* edge_src = (const int*)d_in[1];
    const int* edge_dst = (const int*)d_in[2];
    float* out = (float*)d_out;
    int n_edges = in_sizes[1];

    // Kernel C: fp32 -> fp16 conversion of x
    {
        int threads = 256;
        int work = N_NODES * 32;  // float4 count
        int blocks = (work + threads - 1) / threads;
        convert_kernel<<<blocks, threads>>>((const float4*)x);
    }

    // Kernel A: O(E) boundary-diff offsets, 4 edges/thread
    {
        int threads = 256;
        int work = (n_edges + 3) / 4;
        int blocks = (work + threads - 1) / threads;
        build_offsets_kernel<<<blocks, threads>>>(edge_src, n_edges);
    }

    // Kernel B: one warp per node, 2 warps per block, PDL overlap
    {
        int threads = 64;
        int warps_per_block = threads / 32;
        int blocks = (N_NODES + warps_per_block - 1) / warps_per_block;

        cudaLaunchConfig_t cfg = {};
        cfg.gridDim = dim3(blocks, 1, 1);
        cfg.blockDim = dim3(threads, 1, 1);
        cfg.dynamicSmemBytes = 0;
        cfg.stream = 0;

        cudaLaunchAttribute attr[1];
        attr[0].id = cudaLaunchAttributeProgrammaticStreamSerialization;
        attr[0].val.programmaticStreamSerializationAllowed = 1;
        cfg.attrs = attr;
        cfg.numAttrs = 1;

        cudaLaunchKernelEx(&cfg, graph_pool_kernel,
                           (const float4*)x, edge_dst, (float4*)out);
    }
}

// round 15
// speedup vs baseline: 1.0586x; 1.0586x over previous
#include <cuda_runtime.h>
#include <cuda_fp16.h>
#include <cuda_bf16.h>

#define N_NODES 50000
#define D_FEAT  128

// CSR row offsets into the sorted edge list. 50001 ints.
__device__ int g_offsets[N_NODES + 1];

// fp16 copy of x, same linear layout (12.8 MB scratch).
__device__ __half g_xh[(size_t)N_NODES * D_FEAT];

// Kernel C: convert x (fp32) -> g_xh (fp16). 4 float4s per thread,
// coalesced stride-blockDim, loads front-batched for DRAM MLP.
__global__ void __launch_bounds__(256)
convert_kernel(const float4* __restrict__ x4) {
    const int total = N_NODES * 32;                 // float4 count
    int base = blockIdx.x * (blockDim.x * 4) + threadIdx.x;
    uint2* __restrict__ out = reinterpret_cast<uint2*>(g_xh);

    int i0 = base;
    int i1 = base + 256;
    int i2 = base + 512;
    int i3 = base + 768;

    float4 v0, v1, v2, v3;
    bool p0 = i0 < total, p1 = i1 < total, p2 = i2 < total, p3 = i3 < total;
    if (p0) v0 = x4[i0];
    if (p1) v1 = x4[i1];
    if (p2) v2 = x4[i2];
    if (p3) v3 = x4[i3];

    if (p0) {
        __half2 h0 = __floats2half2_rn(v0.x, v0.y);
        __half2 h1 = __floats2half2_rn(v0.z, v0.w);
        uint2 u; u.x = *reinterpret_cast<unsigned*>(&h0); u.y = *reinterpret_cast<unsigned*>(&h1);
        out[i0] = u;
    }
    if (p1) {
        __half2 h0 = __floats2half2_rn(v1.x, v1.y);
        __half2 h1 = __floats2half2_rn(v1.z, v1.w);
        uint2 u; u.x = *reinterpret_cast<unsigned*>(&h0); u.y = *reinterpret_cast<unsigned*>(&h1);
        out[i1] = u;
    }
    if (p2) {
        __half2 h0 = __floats2half2_rn(v2.x, v2.y);
        __half2 h1 = __floats2half2_rn(v2.z, v2.w);
        uint2 u; u.x = *reinterpret_cast<unsigned*>(&h0); u.y = *reinterpret_cast<unsigned*>(&h1);
        out[i2] = u;
    }
    if (p3) {
        __half2 h0 = __floats2half2_rn(v3.x, v3.y);
        __half2 h1 = __floats2half2_rn(v3.z, v3.w);
        uint2 u; u.x = *reinterpret_cast<unsigned*>(&h0); u.y = *reinterpret_cast<unsigned*>(&h1);
        out[i3] = u;
    }
}

// Kernel A: boundary-diff scatter, 4 edges per thread via int4.
__global__ void build_offsets_kernel(const int* __restrict__ edge_src, int n_edges) {
    int t = blockIdx.x * blockDim.x + threadIdx.x;
    int e0 = t * 4;
    if (e0 >= n_edges) return;
    int4 s = *reinterpret_cast<const int4*>(edge_src + e0);  // n_edges % 4 == 0
    int prev = (e0 == 0) ? -1 : edge_src[e0 - 1];
    for (int n = prev + 1; n <= s.x; n++) g_offsets[n] = e0;
    for (int n = s.x + 1; n <= s.y; n++) g_offsets[n] = e0 + 1;
    for (int n = s.y + 1; n <= s.z; n++) g_offsets[n] = e0 + 2;
    for (int n = s.z + 1; n <= s.w; n++) g_offsets[n] = e0 + 3;
    if (e0 + 4 >= n_edges) {
        for (int n = s.w + 1; n <= N_NODES; n++) g_offsets[n] = n_edges;
    }
}

// Kernel B: one warp per node. Neighbor rows gathered in fp16 (256B rows:
// half the bytes / line-wavefronts of fp32), accumulated in fp32. Self
// feature read exact from fp32 x.
__global__ void __launch_bounds__(64)
graph_pool_kernel(const float4* __restrict__ x,
                  const int* __restrict__ edge_dst,
                  float4* __restrict__ out) {
    int warp_id = (blockIdx.x * blockDim.x + threadIdx.x) >> 5;
    int lane = threadIdx.x & 31;
    if (warp_id >= N_NODES) return;

    // self feature (exact fp32); independent of g_offsets (PDL pre-dep work)
    float4 acc = x[(size_t)warp_id * 32 + lane];

    cudaGridDependencySynchronize();

    int beg = g_offsets[warp_id];
    int end = g_offsets[warp_id + 1];

    const uint2* xh = reinterpret_cast<const uint2*>(g_xh);  // 4 halves/elem

    int e = beg;
    for (; e + 4 <= end; e += 4) {
        int d0 = edge_dst[e + 0];
        int d1 = edge_dst[e + 1];
        int d2 = edge_dst[e + 2];
        int d3 = edge_dst[e + 3];
        uint2 u0 = __ldcg(&xh[(size_t)d0 * 32 + lane]);
        uint2 u1 = __ldcg(&xh[(size_t)d1 * 32 + lane]);
        uint2 u2 = __ldcg(&xh[(size_t)d2 * 32 + lane]);
        uint2 u3 = __ldcg(&xh[(size_t)d3 * 32 + lane]);

        float2 a, b;
        a = __half22float2(*reinterpret_cast<__half2*>(&u0.x));
        b = __half22float2(*reinterpret_cast<__half2*>(&u0.y));
        acc.x += a.x; acc.y += a.y; acc.z += b.x; acc.w += b.y;
        a = __half22float2(*reinterpret_cast<__half2*>(&u1.x));
        b = __half22float2(*reinterpret_cast<__half2*>(&u1.y));
        acc.x += a.x; acc.y += a.y; acc.z += b.x; acc.w += b.y;
        a = __half22float2(*reinterpret_cast<__half2*>(&u2.x));
        b = __half22float2(*reinterpret_cast<__half2*>(&u2.y));
        acc.x += a.x; acc.y += a.y; acc.z += b.x; acc.w += b.y;
        a = __half22float2(*reinterpret_cast<__half2*>(&u3.x));
        b = __half22float2(*reinterpret_cast<__half2*>(&u3.y));
        acc.x += a.x; acc.y += a.y; acc.z += b.x; acc.w += b.y;
    }
    for (; e < end; e++) {
        int d = edge_dst[e];
        uint2 u = __ldcg(&xh[(size_t)d * 32 + lane]);
        float2 a = __half22float2(*reinterpret_cast<__half2*>(&u.x));
        float2 b = __half22float2(*reinterpret_cast<__half2*>(&u.y));
        acc.x += a.x; acc.y += a.y; acc.z += b.x; acc.w += b.y;
    }

    __stcg(&out[(size_t)warp_id * 32 + lane], acc);
}

extern "C" void kernel_launch(void* const* d_in, const int* in_sizes, int n_in,
                              void* d_out, int out_size) {
    const float* x = (const float*)d_in[0];
    const int* edge_src = (const int*)d_in[1];
    const int* edge_dst = (const int*)d_in[2];
    float* out = (float*)d_out;
    int n_edges = in_sizes[1];

    // Kernel C: fp32 -> fp16 conversion of x (4 float4s/thread)
    {
        int threads = 256;
        int work = N_NODES * 32;  // float4 count
        int per_block = threads * 4;
        int blocks = (work + per_block - 1) / per_block;
        convert_kernel<<<blocks, threads>>>((const float4*)x);
    }

    // Kernel A: O(E) boundary-diff offsets, 4 edges/thread
    {
        int threads = 256;
        int work = (n_edges + 3) / 4;
        int blocks = (work + threads - 1) / threads;
        build_offsets_kernel<<<blocks, threads>>>(edge_src, n_edges);
    }

    // Kernel B: one warp per node, 2 warps per block, PDL overlap
    {
        int threads = 64;
        int warps_per_block = threads / 32;
        int blocks = (N_NODES + warps_per_block - 1) / warps_per_block;

        cudaLaunchConfig_t cfg = {};
        cfg.gridDim = dim3(blocks, 1, 1);
        cfg.blockDim = dim3(threads, 1, 1);
        cfg.dynamicSmemBytes = 0;
        cfg.stream = 0;

        cudaLaunchAttribute attr[1];
        attr[0].id = cudaLaunchAttributeProgrammaticStreamSerialization;
        attr[0].val.programmaticStreamSerializationAllowed = 1;
        cfg.attrs = attr;
        cfg.numAttrs = 1;

        cudaLaunchKernelEx(&cfg, graph_pool_kernel,
                           (const float4*)x, edge_dst, (float4*)out);
    }
}

// round 16
// speedup vs baseline: 1.0980x; 1.0372x over previous
#include <cuda_runtime.h>
#include <cuda_fp16.h>
#include <cuda_bf16.h>

#define N_NODES 50000
#define D_FEAT  128

// CSR row offsets into the sorted edge list. 50001 ints.
__device__ int g_offsets[N_NODES + 1];

// fp16 copy of x, same linear layout (12.8 MB scratch).
__device__ __half g_xh[(size_t)N_NODES * D_FEAT];

// Kernel CA (fused prologue): every thread converts 4 float4s of x -> fp16;
// threads t < n_edges/4 additionally do the boundary-diff offsets scatter.
__global__ void __launch_bounds__(256)
prologue_kernel(const float4* __restrict__ x4,
                const int* __restrict__ edge_src, int n_edges) {
    const int total = N_NODES * 32;                 // float4 count = 1.6M
    int t = blockIdx.x * blockDim.x + threadIdx.x;
    uint2* __restrict__ outh = reinterpret_cast<uint2*>(g_xh);

    // ---- offsets diff-scatter (first n_edges/4 threads) ----
    int e0 = t * 4;
    if (e0 < n_edges) {
        int4 s = *reinterpret_cast<const int4*>(edge_src + e0);  // n_edges%4==0
        int prev = (e0 == 0) ? -1 : edge_src[e0 - 1];
        for (int n = prev + 1; n <= s.x; n++) g_offsets[n] = e0;
        for (int n = s.x + 1; n <= s.y; n++) g_offsets[n] = e0 + 1;
        for (int n = s.y + 1; n <= s.z; n++) g_offsets[n] = e0 + 2;
        for (int n = s.z + 1; n <= s.w; n++) g_offsets[n] = e0 + 3;
        if (e0 + 4 >= n_edges) {
            for (int n = s.w + 1; n <= N_NODES; n++) g_offsets[n] = n_edges;
        }
    }

    // ---- fp32 -> fp16 conversion, 4 float4s per thread, block-striped ----
    int base = blockIdx.x * (blockDim.x * 4) + threadIdx.x;
    #pragma unroll
    for (int k = 0; k < 4; k++) {
        int i = base + k * 256;
        if (i < total) {
            float4 v = x4[i];
            __half2 h0 = __floats2half2_rn(v.x, v.y);
            __half2 h1 = __floats2half2_rn(v.z, v.w);
            uint2 u;
            u.x = *reinterpret_cast<unsigned*>(&h0);
            u.y = *reinterpret_cast<unsigned*>(&h1);
            outh[i] = u;
        }
    }
}

// Kernel B: one warp per node, unroll-8 fp16 row gathers (256B rows = 2
// line-wavefronts each; 8 in flight = 16 wf/warp, same queue depth as the
// proven fp32 unroll-4), fp32 accumulate, exact fp32 self feature.
__global__ void __launch_bounds__(64)
graph_pool_kernel(const float4* __restrict__ x,
                  const int* __restrict__ edge_dst,
                  float4* __restrict__ out) {
    int warp_id = (blockIdx.x * blockDim.x + threadIdx.x) >> 5;
    int lane = threadIdx.x & 31;
    if (warp_id >= N_NODES) return;

    // self feature (exact fp32); independent of prologue (PDL pre-dep work)
    float4 acc = x[(size_t)warp_id * 32 + lane];

    cudaGridDependencySynchronize();

    int beg = g_offsets[warp_id];
    int end = g_offsets[warp_id + 1];

    const uint2* xh = reinterpret_cast<const uint2*>(g_xh);  // 4 halves/elem
    float4 acc1 = make_float4(0.f, 0.f, 0.f, 0.f);

    int e = beg;
    for (; e + 8 <= end; e += 8) {
        int d0 = edge_dst[e + 0];
        int d1 = edge_dst[e + 1];
        int d2 = edge_dst[e + 2];
        int d3 = edge_dst[e + 3];
        int d4 = edge_dst[e + 4];
        int d5 = edge_dst[e + 5];
        int d6 = edge_dst[e + 6];
        int d7 = edge_dst[e + 7];
        uint2 u0 = __ldcg(&xh[(size_t)d0 * 32 + lane]);
        uint2 u1 = __ldcg(&xh[(size_t)d1 * 32 + lane]);
        uint2 u2 = __ldcg(&xh[(size_t)d2 * 32 + lane]);
        uint2 u3 = __ldcg(&xh[(size_t)d3 * 32 + lane]);
        uint2 u4 = __ldcg(&xh[(size_t)d4 * 32 + lane]);
        uint2 u5 = __ldcg(&xh[(size_t)d5 * 32 + lane]);
        uint2 u6 = __ldcg(&xh[(size_t)d6 * 32 + lane]);
        uint2 u7 = __ldcg(&xh[(size_t)d7 * 32 + lane]);

        float2 a, b;
        a = __half22float2(*reinterpret_cast<__half2*>(&u0.x));
        b = __half22float2(*reinterpret_cast<__half2*>(&u0.y));
        acc.x += a.x; acc.y += a.y; acc.z += b.x; acc.w += b.y;
        a = __half22float2(*reinterpret_cast<__half2*>(&u1.x));
        b = __half22float2(*reinterpret_cast<__half2*>(&u1.y));
        acc1.x += a.x; acc1.y += a.y; acc1.z += b.x; acc1.w += b.y;
        a = __half22float2(*reinterpret_cast<__half2*>(&u2.x));
        b = __half22float2(*reinterpret_cast<__half2*>(&u2.y));
        acc.x += a.x; acc.y += a.y; acc.z += b.x; acc.w += b.y;
        a = __half22float2(*reinterpret_cast<__half2*>(&u3.x));
        b = __half22float2(*reinterpret_cast<__half2*>(&u3.y));
        acc1.x += a.x; acc1.y += a.y; acc1.z += b.x; acc1.w += b.y;
        a = __half22float2(*reinterpret_cast<__half2*>(&u4.x));
        b = __half22float2(*reinterpret_cast<__half2*>(&u4.y));
        acc.x += a.x; acc.y += a.y; acc.z += b.x; acc.w += b.y;
        a = __half22float2(*reinterpret_cast<__half2*>(&u5.x));
        b = __half22float2(*reinterpret_cast<__half2*>(&u5.y));
        acc1.x += a.x; acc1.y += a.y; acc1.z += b.x; acc1.w += b.y;
        a = __half22float2(*reinterpret_cast<__half2*>(&u6.x));
        b = __half22float2(*reinterpret_cast<__half2*>(&u6.y));
        acc.x += a.x; acc.y += a.y; acc.z += b.x; acc.w += b.y;
        a = __half22float2(*reinterpret_cast<__half2*>(&u7.x));
        b = __half22float2(*reinterpret_cast<__half2*>(&u7.y));
        acc1.x += a.x; acc1.y += a.y; acc1.z += b.x; acc1.w += b.y;
    }
    for (; e < end; e++) {
        int d = edge_dst[e];
        uint2 u = __ldcg(&xh[(size_t)d * 32 + lane]);
        float2 a = __half22float2(*reinterpret_cast<__half2*>(&u.x));
        float2 b = __half22float2(*reinterpret_cast<__half2*>(&u.y));
        acc.x += a.x; acc.y += a.y; acc.z += b.x; acc.w += b.y;
    }

    acc.x += acc1.x; acc.y += acc1.y; acc.z += acc1.z; acc.w += acc1.w;
    __stcg(&out[(size_t)warp_id * 32 + lane], acc);
}

extern "C" void kernel_launch(void* const* d_in, const int* in_sizes, int n_in,
                              void* d_out, int out_size) {
    const float* x = (const float*)d_in[0];
    const int* edge_src = (const int*)d_in[1];
    const int* edge_dst = (const int*)d_in[2];
    float* out = (float*)d_out;
    int n_edges = in_sizes[1];

    // Fused prologue: fp16 conversion + offsets scatter, one launch
    {
        int threads = 256;
        int work = N_NODES * 32;            // float4 count
        int per_block = threads * 4;
        int blocks = (work + per_block - 1) / per_block;
        prologue_kernel<<<blocks, threads>>>((const float4*)x, edge_src, n_edges);
    }

    // Kernel B: one warp per node, 2 warps per block, PDL overlap
    {
        int threads = 64;
        int warps_per_block = threads / 32;
        int blocks = (N_NODES + warps_per_block - 1) / warps_per_block;

        cudaLaunchConfig_t cfg = {};
        cfg.gridDim = dim3(blocks, 1, 1);
        cfg.blockDim = dim3(threads, 1, 1);
        cfg.dynamicSmemBytes = 0;
        cfg.stream = 0;

        cudaLaunchAttribute attr[1];
        attr[0].id = cudaLaunchAttributeProgrammaticStreamSerialization;
        attr[0].val.programmaticStreamSerializationAllowed = 1;
        cfg.attrs = attr;
        cfg.numAttrs = 1;

        cudaLaunchKernelEx(&cfg, graph_pool_kernel,
                           (const float4*)x, edge_dst, (float4*)out);
    }
}

// round 17
// speedup vs baseline: 1.2420x; 1.1312x over previous
#include <cuda_runtime.h>
#include <cuda_fp16.h>
#include <cuda_bf16.h>

#define N_NODES 50000
#define D_FEAT  128

// CSR row offsets into the sorted edge list. 50001 ints.
__device__ int g_offsets[N_NODES + 1];

// fp16 copy of x, same linear layout (12.8 MB scratch).
__device__ __half g_xh[(size_t)N_NODES * D_FEAT];

// Fused prologue: every thread converts 4 float4s of x -> fp16 (written as
// 2 uint4 stores); threads t < n_edges/4 also do the offsets diff-scatter.
__global__ void __launch_bounds__(256)
prologue_kernel(const float4* __restrict__ x4,
                const int* __restrict__ edge_src, int n_edges) {
    const int total = N_NODES * 32;                 // float4 count = 1.6M
    int t = blockIdx.x * blockDim.x + threadIdx.x;

    // ---- offsets diff-scatter (first n_edges/4 threads) ----
    int e0 = t * 4;
    if (e0 < n_edges) {
        int4 s = *reinterpret_cast<const int4*>(edge_src + e0);  // n_edges%4==0
        int prev = (e0 == 0) ? -1 : edge_src[e0 - 1];
        for (int n = prev + 1; n <= s.x; n++) g_offsets[n] = e0;
        for (int n = s.x + 1; n <= s.y; n++) g_offsets[n] = e0 + 1;
        for (int n = s.y + 1; n <= s.z; n++) g_offsets[n] = e0 + 2;
        for (int n = s.z + 1; n <= s.w; n++) g_offsets[n] = e0 + 3;
        if (e0 + 4 >= n_edges) {
            for (int n = s.w + 1; n <= N_NODES; n++) g_offsets[n] = n_edges;
        }
    }

    // ---- fp32 -> fp16, 4 float4s/thread, paired into uint4 stores ----
    int base = blockIdx.x * (blockDim.x * 4) + threadIdx.x;
    uint4* __restrict__ outh4 = reinterpret_cast<uint4*>(g_xh);
    #pragma unroll
    for (int k = 0; k < 2; k++) {
        int i = base + k * 512;          // pair (i, i+256): consecutive? no —
        // must pair CONSECUTIVE float4s for a contiguous uint4. Use stride-2:
        int j = blockIdx.x * (blockDim.x * 4) + threadIdx.x * 2 + k * 512;
        // j, j+1 are consecutive float4 indices
        if (j + 1 < total) {
            float4 a = x4[j];
            float4 b = x4[j + 1];
            __half2 h0 = __floats2half2_rn(a.x, a.y);
            __half2 h1 = __floats2half2_rn(a.z, a.w);
            __half2 h2 = __floats2half2_rn(b.x, b.y);
            __half2 h3 = __floats2half2_rn(b.z, b.w);
            uint4 u;
            u.x = *reinterpret_cast<unsigned*>(&h0);
            u.y = *reinterpret_cast<unsigned*>(&h1);
            u.z = *reinterpret_cast<unsigned*>(&h2);
            u.w = *reinterpret_cast<unsigned*>(&h3);
            outh4[j >> 1] = u;
        } else if (j < total) {
            float4 a = x4[j];
            __half2 h0 = __floats2half2_rn(a.x, a.y);
            __half2 h1 = __floats2half2_rn(a.z, a.w);
            uint2 u;
            u.x = *reinterpret_cast<unsigned*>(&h0);
            u.y = *reinterpret_cast<unsigned*>(&h1);
            reinterpret_cast<uint2*>(g_xh)[j] = u;
        }
    }
}

static __device__ __forceinline__ __half2 U2H(unsigned u) {
    return *reinterpret_cast<__half2*>(&u);
}

// Kernel B: one warp per node, unroll-8 fp16 gathers. Accumulation via
// HADD2 trees (7 ops per position per 8 edges) folded into fp32 once per
// group — ~2.2x fewer accumulate issue slots than scalar convert+FADD.
__global__ void __launch_bounds__(64)
graph_pool_kernel(const float4* __restrict__ x,
                  const int* __restrict__ edge_dst,
                  float4* __restrict__ out) {
    int warp_id = (blockIdx.x * blockDim.x + threadIdx.x) >> 5;
    int lane = threadIdx.x & 31;
    if (warp_id >= N_NODES) return;

    // self feature (exact fp32); PDL pre-dependency work
    float4 acc = x[(size_t)warp_id * 32 + lane];

    cudaGridDependencySynchronize();

    int beg = g_offsets[warp_id];
    int end = g_offsets[warp_id + 1];

    const uint2* xh = reinterpret_cast<const uint2*>(g_xh);  // 4 halves/elem

    int e = beg;
    for (; e + 8 <= end; e += 8) {
        int d0 = edge_dst[e + 0];
        int d1 = edge_dst[e + 1];
        int d2 = edge_dst[e + 2];
        int d3 = edge_dst[e + 3];
        int d4 = edge_dst[e + 4];
        int d5 = edge_dst[e + 5];
        int d6 = edge_dst[e + 6];
        int d7 = edge_dst[e + 7];
        uint2 u0 = __ldcg(&xh[(size_t)d0 * 32 + lane]);
        uint2 u1 = __ldcg(&xh[(size_t)d1 * 32 + lane]);
        uint2 u2 = __ldcg(&xh[(size_t)d2 * 32 + lane]);
        uint2 u3 = __ldcg(&xh[(size_t)d3 * 32 + lane]);
        uint2 u4 = __ldcg(&xh[(size_t)d4 * 32 + lane]);
        uint2 u5 = __ldcg(&xh[(size_t)d5 * 32 + lane]);
        uint2 u6 = __ldcg(&xh[(size_t)d6 * 32 + lane]);
        uint2 u7 = __ldcg(&xh[(size_t)d7 * 32 + lane]);

        // HADD2 tree, position X (feats lane*4+0,1)
        __half2 tx0 = __hadd2(U2H(u0.x), U2H(u1.x));
        __half2 tx1 = __hadd2(U2H(u2.x), U2H(u3.x));
        __half2 tx2 = __hadd2(U2H(u4.x), U2H(u5.x));
        __half2 tx3 = __hadd2(U2H(u6.x), U2H(u7.x));
        __half2 tx = __hadd2(__hadd2(tx0, tx1), __hadd2(tx2, tx3));
        // position Y (feats lane*4+2,3)
        __half2 ty0 = __hadd2(U2H(u0.y), U2H(u1.y));
        __half2 ty1 = __hadd2(U2H(u2.y), U2H(u3.y));
        __half2 ty2 = __hadd2(U2H(u4.y), U2H(u5.y));
        __half2 ty3 = __hadd2(U2H(u6.y), U2H(u7.y));
        __half2 ty = __hadd2(__hadd2(ty0, ty1), __hadd2(ty2, ty3));

        float2 fx = __half22float2(tx);
        float2 fy = __half22float2(ty);
        acc.x += fx.x; acc.y += fx.y; acc.z += fy.x; acc.w += fy.y;
    }
    if (e + 4 <= end) {
        int d0 = edge_dst[e + 0];
        int d1 = edge_dst[e + 1];
        int d2 = edge_dst[e + 2];
        int d3 = edge_dst[e + 3];
        uint2 u0 = __ldcg(&xh[(size_t)d0 * 32 + lane]);
        uint2 u1 = __ldcg(&xh[(size_t)d1 * 32 + lane]);
        uint2 u2 = __ldcg(&xh[(size_t)d2 * 32 + lane]);
        uint2 u3 = __ldcg(&xh[(size_t)d3 * 32 + lane]);
        __half2 tx = __hadd2(__hadd2(U2H(u0.x), U2H(u1.x)),
                             __hadd2(U2H(u2.x), U2H(u3.x)));
        __half2 ty = __hadd2(__hadd2(U2H(u0.y), U2H(u1.y)),
                             __hadd2(U2H(u2.y), U2H(u3.y)));
        float2 fx = __half22float2(tx);
        float2 fy = __half22float2(ty);
        acc.x += fx.x; acc.y += fx.y; acc.z += fy.x; acc.w += fy.y;
        e += 4;
    }
    for (; e < end; e++) {
        int d = edge_dst[e];
        uint2 u = __ldcg(&xh[(size_t)d * 32 + lane]);
        float2 a = __half22float2(U2H(u.x));
        float2 b = __half22float2(U2H(u.y));
        acc.x += a.x; acc.y += a.y; acc.z += b.x; acc.w += b.y;
    }

    __stcg(&out[(size_t)warp_id * 32 + lane], acc);
}

extern "C" void kernel_launch(void* const* d_in, const int* in_sizes, int n_in,
                              void* d_out, int out_size) {
    const float* x = (const float*)d_in[0];
    const int* edge_src = (const int*)d_in[1];
    const int* edge_dst = (const int*)d_in[2];
    float* out = (float*)d_out;
    int n_edges = in_sizes[1];

    // Fused prologue: fp16 conversion + offsets scatter, one launch
    {
        int threads = 256;
        int work = N_NODES * 32;            // float4 count
        int per_block = threads * 4;
        int blocks = (work + per_block - 1) / per_block;
        prologue_kernel<<<blocks, threads>>>((const float4*)x, edge_src, n_edges);
    }

    // Kernel B: one warp per node, 2 warps per block, PDL overlap
    {
        int threads = 64;
        int warps_per_block = threads / 32;
        int blocks = (N_NODES + warps_per_block - 1) / warps_per_block;

        cudaLaunchConfig_t cfg = {};
        cfg.gridDim = dim3(blocks, 1, 1);
        cfg.blockDim = dim3(threads, 1, 1);
        cfg.dynamicSmemBytes = 0;
        cfg.stream = 0;

        cudaLaunchAttribute attr[1];
        attr[0].id = cudaLaunchAttributeProgrammaticStreamSerialization;
        attr[0].val.programmaticStreamSerializationAllowed = 1;
        cfg.attrs = attr;
        cfg.numAttrs = 1;

        cudaLaunchKernelEx(&cfg, graph_pool_kernel,
                           (const float4*)x, edge_dst, (float4*)out);
    }
}